// round 5
// baseline (speedup 1.0000x reference)
#include <cuda_runtime.h>
#include <math.h>
#include <stdint.h>

#define B_   8
#define S_   512
#define HID_ 768
#define H_   12
#define D_   64
#define BS_  (B_*S_)          // 4096
#define BH_  (B_*H_)          // 96

#define CTX_ELEMS ((size_t)B_*S_*HID_)        // 3,145,728
#define SC_ELEMS  ((size_t)BH_*S_*S_)         // 25,165,824

// Scratch (device globals — no allocation in kernel_launch)
__device__ float g_q[BH_*S_*D_];
__device__ float g_k[BH_*S_*D_];
__device__ float g_v[BH_*S_*D_];

__device__ __forceinline__ float to_tf32(float x) {
    float r;
    asm("cvt.rna.tf32.f32 %0, %1;" : "=f"(r) : "f"(x));
    return r;
}

__device__ __forceinline__ void split_tf32(float x, float& hi, float& lo) {
    float h;
    asm("cvt.rna.tf32.f32 %0, %1;" : "=f"(h) : "f"(x));
    float l = x - h;                    // exact in fp32
    asm("cvt.rna.tf32.f32 %0, %1;" : "=f"(lo) : "f"(l));
    hi = h;
}

__device__ __forceinline__ void mma_tf32(float* c, const uint32_t* a, const uint32_t* b) {
    asm volatile(
        "mma.sync.aligned.m16n8k8.row.col.f32.tf32.tf32.f32 "
        "{%0,%1,%2,%3}, {%4,%5,%6,%7}, {%8,%9}, {%0,%1,%2,%3};\n"
        : "+f"(c[0]), "+f"(c[1]), "+f"(c[2]), "+f"(c[3])
        : "r"(a[0]), "r"(a[1]), "r"(a[2]), "r"(a[3]), "r"(b[0]), "r"(b[1]));
}

// ---------------------------------------------------------------------------
// Kernel 1: QKV projection via 3xTF32 MMA.
// hi/lo split once at load, stored INTERLEAVED (float2) -> LDS.64 fragments.
// Block 128(m) x 128(n), BK=16. 256 threads = 8 warps (2m x 4n), warp 64x32.
// Row stride 40 floats (= 8 mod 32 banks): conflict-free LDS.64 per 16-lane phase.
// grid: (6, 32, 3).
// ---------------------------------------------------------------------------
__global__ void __launch_bounds__(256, 2)
qkv_mma(const float* __restrict__ hid,
        const float* __restrict__ Wq, const float* __restrict__ bq,
        const float* __restrict__ Wk, const float* __restrict__ bk,
        const float* __restrict__ Wv, const float* __restrict__ bv)
{
    const int z = blockIdx.z;
    const float* W    = (z == 0) ? Wq : ((z == 1) ? Wk : Wv);
    const float* bias = (z == 0) ? bq : ((z == 1) ? bk : bv);
    float* out        = (z == 0) ? g_q : ((z == 1) ? g_k : g_v);

    const int m0 = blockIdx.y * 128;
    const int n0 = blockIdx.x * 128;

    // [buf][row][2k + (0:hi,1:lo)] ; row stride 40 floats = 160B
    __shared__ float Ai[2][128][40];
    __shared__ float Bi[2][128][40];

    const int tid  = threadIdx.x;
    const int lane = tid & 31;
    const int wid  = tid >> 5;
    const int gr   = lane >> 2;
    const int gc   = lane & 3;
    const int wm   = (wid & 1) * 64;
    const int wn   = (wid >> 1) * 32;

    const int lrow = tid >> 2;          // 0..63
    const int lq   = (tid & 3) * 4;     // k-offset 0,4,8,12

    float c[4][4][4];
    #pragma unroll
    for (int im = 0; im < 4; im++)
        #pragma unroll
        for (int jn = 0; jn < 4; jn++)
            #pragma unroll
            for (int r = 0; r < 4; r++) c[im][jn][r] = 0.0f;

    float4 ra0, ra1, rb0, rb1;

    #define LDG_TILE(k0)                                                           \
        ra0 = *(const float4*)(hid + (size_t)(m0 + lrow)      * HID_ + (k0) + lq); \
        ra1 = *(const float4*)(hid + (size_t)(m0 + lrow + 64) * HID_ + (k0) + lq); \
        rb0 = *(const float4*)(W   + (size_t)(n0 + lrow)      * HID_ + (k0) + lq); \
        rb1 = *(const float4*)(W   + (size_t)(n0 + lrow + 64) * HID_ + (k0) + lq);

    #define STS_ONE(arr, buf, row, v)                                              \
    {                                                                               \
        float h0,l0,h1,l1,h2,l2,h3,l3;                                              \
        split_tf32(v.x,h0,l0); split_tf32(v.y,h1,l1);                               \
        split_tf32(v.z,h2,l2); split_tf32(v.w,h3,l3);                               \
        *(float4*)&arr[buf][row][2*lq    ] = make_float4(h0,l0,h1,l1);              \
        *(float4*)&arr[buf][row][2*lq + 4] = make_float4(h2,l2,h3,l3);              \
    }

    #define STS_SPLIT(buf)                                                          \
        STS_ONE(Ai, buf, lrow,      ra0)                                            \
        STS_ONE(Ai, buf, lrow + 64, ra1)                                            \
        STS_ONE(Bi, buf, lrow,      rb0)                                            \
        STS_ONE(Bi, buf, lrow + 64, rb1)

    LDG_TILE(0)
    STS_SPLIT(0)
    __syncthreads();

    const int NIT = HID_ / 16;   // 48
    for (int it = 0; it < NIT; it++) {
        const int buf = it & 1;
        if (it + 1 < NIT) { LDG_TILE((it + 1) * 16) }

        #pragma unroll
        for (int ks = 0; ks < 16; ks += 8) {
            const int c0 = 2 * (ks + gc);       // interleaved float col
            uint32_t ahi[4][4], alo[4][4], bhi[4][2], blo[4][2];
            #pragma unroll
            for (int im = 0; im < 4; im++) {
                int r = wm + im * 16 + gr;
                float2 t;
                t = *(float2*)&Ai[buf][r    ][c0    ]; ahi[im][0] = __float_as_uint(t.x); alo[im][0] = __float_as_uint(t.y);
                t = *(float2*)&Ai[buf][r + 8][c0    ]; ahi[im][1] = __float_as_uint(t.x); alo[im][1] = __float_as_uint(t.y);
                t = *(float2*)&Ai[buf][r    ][c0 + 8]; ahi[im][2] = __float_as_uint(t.x); alo[im][2] = __float_as_uint(t.y);
                t = *(float2*)&Ai[buf][r + 8][c0 + 8]; ahi[im][3] = __float_as_uint(t.x); alo[im][3] = __float_as_uint(t.y);
            }
            #pragma unroll
            for (int jn = 0; jn < 4; jn++) {
                int n = wn + jn * 8 + gr;
                float2 t;
                t = *(float2*)&Bi[buf][n][c0    ]; bhi[jn][0] = __float_as_uint(t.x); blo[jn][0] = __float_as_uint(t.y);
                t = *(float2*)&Bi[buf][n][c0 + 8]; bhi[jn][1] = __float_as_uint(t.x); blo[jn][1] = __float_as_uint(t.y);
            }
            #pragma unroll
            for (int im = 0; im < 4; im++)
                #pragma unroll
                for (int jn = 0; jn < 4; jn++) {
                    mma_tf32(c[im][jn], ahi[im], bhi[jn]);
                    mma_tf32(c[im][jn], ahi[im], blo[jn]);
                    mma_tf32(c[im][jn], alo[im], bhi[jn]);
                }
        }

        if (it + 1 < NIT) { STS_SPLIT((it + 1) & 1) }
        __syncthreads();
    }
    #undef LDG_TILE
    #undef STS_ONE
    #undef STS_SPLIT

    // Epilogue: + bias, scatter to [B,H,S,D]. Warp n-span (32) never crosses a head.
    const int h      = (n0 + wn) >> 6;
    const int d_base = (n0 + wn) & 63;
    #pragma unroll
    for (int jn = 0; jn < 4; jn++) {
        int d = d_base + jn * 8 + gc * 2;
        float b0 = bias[n0 + wn + jn * 8 + gc * 2];
        float b1 = bias[n0 + wn + jn * 8 + gc * 2 + 1];
        #pragma unroll
        for (int im = 0; im < 4; im++) {
            int m = m0 + wm + im * 16 + gr;
            int b = m >> 9;
            int s = m & 511;
            float* o = out + (((size_t)(b * H_ + h) * S_ + s) * D_ + d);
            *(float2*)o            = make_float2(c[im][jn][0] + b0, c[im][jn][1] + b1);
            *(float2*)(o + 8 * D_) = make_float2(c[im][jn][2] + b0, c[im][jn][3] + b1);
        }
    }
}

// ---------------------------------------------------------------------------
// Kernel 2: self-similarity scores (qq, kk, vv) via tf32 mma.
// C = 0.125*X@X^T + mask. Block: 64(q) x 128(k), 256 threads (8 warps 2x4).
// grid: (4, 8, 3*96).
// ---------------------------------------------------------------------------
__global__ void __launch_bounds__(256)
scores_sim(const float* __restrict__ mask, float* __restrict__ out_base)
{
    const int z    = blockIdx.z;
    const int type = 1 + z / BH_;       // 1:qq 2:kk 3:vv
    const int bh   = z % BH_;

    const float* X = (type == 1) ? g_q : ((type == 2) ? g_k : g_v);
    X += (size_t)bh * S_ * D_;

    float* out = out_base + (size_t)type * SC_ELEMS + (size_t)bh * S_ * S_;
    const float* mrow = mask + (size_t)(bh / H_) * S_;

    const int m0 = blockIdx.y * 64;
    const int n0 = blockIdx.x * 128;

    __shared__ float Xs[64][68];
    __shared__ float Ys[128][68];

    const int tid = threadIdx.x;

    #pragma unroll
    for (int r = 0; r < 4; r++) {
        int idx = tid + 256 * r;
        int row = idx >> 4;
        int q   = idx & 15;
        float4 a = *(const float4*)(X + (size_t)(m0 + row) * D_ + q * 4);
        Xs[row][q*4+0] = to_tf32(a.x); Xs[row][q*4+1] = to_tf32(a.y);
        Xs[row][q*4+2] = to_tf32(a.z); Xs[row][q*4+3] = to_tf32(a.w);
    }
    #pragma unroll
    for (int r = 0; r < 8; r++) {
        int idx = tid + 256 * r;
        int row = idx >> 4;
        int q   = idx & 15;
        float4 b = *(const float4*)(X + (size_t)(n0 + row) * D_ + q * 4);
        Ys[row][q*4+0] = to_tf32(b.x); Ys[row][q*4+1] = to_tf32(b.y);
        Ys[row][q*4+2] = to_tf32(b.z); Ys[row][q*4+3] = to_tf32(b.w);
    }
    __syncthreads();

    const int lane = tid & 31;
    const int wid  = tid >> 5;
    const int wm   = (wid & 1) * 32;
    const int wn   = (wid >> 1) * 32;
    const int gr   = lane >> 2;
    const int gc   = lane & 3;

    float c[2][4][4];
    #pragma unroll
    for (int im = 0; im < 2; im++)
        #pragma unroll
        for (int jn = 0; jn < 4; jn++)
            #pragma unroll
            for (int r = 0; r < 4; r++) c[im][jn][r] = 0.0f;

    #pragma unroll
    for (int k0 = 0; k0 < 64; k0 += 8) {
        uint32_t a[2][4], b[4][2];
        #pragma unroll
        for (int im = 0; im < 2; im++) {
            int r0 = wm + im * 16 + gr;
            a[im][0] = __float_as_uint(Xs[r0    ][k0 + gc    ]);
            a[im][1] = __float_as_uint(Xs[r0 + 8][k0 + gc    ]);
            a[im][2] = __float_as_uint(Xs[r0    ][k0 + gc + 4]);
            a[im][3] = __float_as_uint(Xs[r0 + 8][k0 + gc + 4]);
        }
        #pragma unroll
        for (int jn = 0; jn < 4; jn++) {
            int n = wn + jn * 8 + gr;
            b[jn][0] = __float_as_uint(Ys[n][k0 + gc    ]);
            b[jn][1] = __float_as_uint(Ys[n][k0 + gc + 4]);
        }
        #pragma unroll
        for (int im = 0; im < 2; im++)
            #pragma unroll
            for (int jn = 0; jn < 4; jn++)
                mma_tf32(c[im][jn], a[im], b[jn]);
    }

    #pragma unroll
    for (int im = 0; im < 2; im++) {
        #pragma unroll
        for (int jn = 0; jn < 4; jn++) {
            int row = m0 + wm + im * 16 + gr;
            int col = n0 + wn + jn * 8 + gc * 2;
            float mv0 = mrow[col], mv1 = mrow[col + 1];
            float2 o0 = make_float2(c[im][jn][0] * 0.125f + mv0,
                                    c[im][jn][1] * 0.125f + mv1);
            float2 o1 = make_float2(c[im][jn][2] * 0.125f + mv0,
                                    c[im][jn][3] * 0.125f + mv1);
            *(float2*)(out + (size_t)row * S_ + col)       = o0;
            *(float2*)(out + (size_t)(row + 8) * S_ + col) = o1;
        }
    }
}

// ---------------------------------------------------------------------------
// Kernel 3: fused qk-scores + softmax + P@V, all-MMA (tf32).
// Per block: 64 q-rows of one (b,h). Writes scores(qk) tile AND ctx.
// 128 threads = 4 warps; warp w owns rows [16w,16w+16).
// grid: (8, 96).
// ---------------------------------------------------------------------------
__global__ void __launch_bounds__(128)
flash_attn(const float* __restrict__ mask, float* __restrict__ sout_base,
           float* __restrict__ ctx)
{
    const int bh = blockIdx.y;
    const int q0 = blockIdx.x * 64;
    const int b  = bh / H_;
    const int h  = bh - b * H_;
    const float* Qp = g_q + (size_t)bh * S_ * D_;
    const float* Kp = g_k + (size_t)bh * S_ * D_;
    const float* Vp = g_v + (size_t)bh * S_ * D_;
    float* sout = sout_base + (size_t)bh * S_ * S_;
    const float* mrow = mask + (size_t)b * S_;

    __shared__ float QPs[64][68];   // Q tile, then reused as P tile
    __shared__ float Ks[64][68];
    __shared__ float Vs[64][72];

    const int tid  = threadIdx.x;
    const int lane = tid & 31;
    const int w    = tid >> 5;
    const int gr   = lane >> 2;
    const int gc   = lane & 3;

    #pragma unroll
    for (int r = 0; r < 8; r++) {
        int idx = tid + 128 * r;
        int row = idx >> 4;
        int q   = idx & 15;
        float4 a = *(const float4*)(Qp + (size_t)(q0 + row) * D_ + q * 4);
        QPs[row][q*4+0] = to_tf32(a.x); QPs[row][q*4+1] = to_tf32(a.y);
        QPs[row][q*4+2] = to_tf32(a.z); QPs[row][q*4+3] = to_tf32(a.w);
    }
    __syncthreads();

    uint32_t aq[8][4];
    #pragma unroll
    for (int ks = 0; ks < 8; ks++) {
        int r0 = w * 16 + gr;
        aq[ks][0] = __float_as_uint(QPs[r0    ][8*ks + gc    ]);
        aq[ks][1] = __float_as_uint(QPs[r0 + 8][8*ks + gc    ]);
        aq[ks][2] = __float_as_uint(QPs[r0    ][8*ks + gc + 4]);
        aq[ks][3] = __float_as_uint(QPs[r0 + 8][8*ks + gc + 4]);
    }

    float o[8][4];
    #pragma unroll
    for (int jd = 0; jd < 8; jd++)
        #pragma unroll
        for (int r = 0; r < 4; r++) o[jd][r] = 0.0f;

    float m0 = -1e30f, m1 = -1e30f, l0 = 0.0f, l1 = 0.0f;
    const int rowg = q0 + w * 16 + gr;

    for (int kt = 0; kt < 8; kt++) {
        #pragma unroll
        for (int r = 0; r < 8; r++) {
            int idx = tid + 128 * r;
            int row = idx >> 4;
            int q   = idx & 15;
            float4 kv = *(const float4*)(Kp + (size_t)(kt*64 + row) * D_ + q * 4);
            Ks[row][q*4+0] = to_tf32(kv.x); Ks[row][q*4+1] = to_tf32(kv.y);
            Ks[row][q*4+2] = to_tf32(kv.z); Ks[row][q*4+3] = to_tf32(kv.w);
            float4 vv = *(const float4*)(Vp + (size_t)(kt*64 + row) * D_ + q * 4);
            Vs[row][q*4+0] = to_tf32(vv.x); Vs[row][q*4+1] = to_tf32(vv.y);
            Vs[row][q*4+2] = to_tf32(vv.z); Vs[row][q*4+3] = to_tf32(vv.w);
        }
        __syncthreads();

        float s[8][4];
        #pragma unroll
        for (int jn = 0; jn < 8; jn++) {
            #pragma unroll
            for (int r = 0; r < 4; r++) s[jn][r] = 0.0f;
            #pragma unroll
            for (int ks = 0; ks < 8; ks++) {
                uint32_t bv[2];
                bv[0] = __float_as_uint(Ks[jn*8 + gr][8*ks + gc    ]);
                bv[1] = __float_as_uint(Ks[jn*8 + gr][8*ks + gc + 4]);
                mma_tf32(s[jn], aq[ks], bv);
            }
        }

        float mx0 = -1e30f, mx1 = -1e30f;
        #pragma unroll
        for (int jn = 0; jn < 8; jn++) {
            int col = kt*64 + jn*8 + gc*2;
            float mv0 = mrow[col], mv1 = mrow[col + 1];
            s[jn][0] = s[jn][0]*0.125f + mv0;  s[jn][1] = s[jn][1]*0.125f + mv1;
            s[jn][2] = s[jn][2]*0.125f + mv0;  s[jn][3] = s[jn][3]*0.125f + mv1;
            *(float2*)(sout + (size_t)rowg       * S_ + col) = make_float2(s[jn][0], s[jn][1]);
            *(float2*)(sout + (size_t)(rowg + 8) * S_ + col) = make_float2(s[jn][2], s[jn][3]);
            mx0 = fmaxf(mx0, fmaxf(s[jn][0], s[jn][1]));
            mx1 = fmaxf(mx1, fmaxf(s[jn][2], s[jn][3]));
        }
        mx0 = fmaxf(mx0, __shfl_xor_sync(0xffffffffu, mx0, 1));
        mx0 = fmaxf(mx0, __shfl_xor_sync(0xffffffffu, mx0, 2));
        mx1 = fmaxf(mx1, __shfl_xor_sync(0xffffffffu, mx1, 1));
        mx1 = fmaxf(mx1, __shfl_xor_sync(0xffffffffu, mx1, 2));

        float mn0 = fmaxf(m0, mx0), mn1 = fmaxf(m1, mx1);
        float sc0 = __expf(m0 - mn0), sc1 = __expf(m1 - mn1);

        float ps0 = 0.0f, ps1 = 0.0f;
        #pragma unroll
        for (int jn = 0; jn < 8; jn++) {
            float p0 = __expf(s[jn][0] - mn0), p1 = __expf(s[jn][1] - mn0);
            float p2 = __expf(s[jn][2] - mn1), p3 = __expf(s[jn][3] - mn1);
            ps0 += p0 + p1;  ps1 += p2 + p3;
            int col = jn*8 + gc*2;
            int r0  = w*16 + gr;
            *(float2*)&QPs[r0    ][col] = make_float2(to_tf32(p0), to_tf32(p1));
            *(float2*)&QPs[r0 + 8][col] = make_float2(to_tf32(p2), to_tf32(p3));
        }
        ps0 += __shfl_xor_sync(0xffffffffu, ps0, 1);
        ps0 += __shfl_xor_sync(0xffffffffu, ps0, 2);
        ps1 += __shfl_xor_sync(0xffffffffu, ps1, 1);
        ps1 += __shfl_xor_sync(0xffffffffu, ps1, 2);
        l0 = l0 * sc0 + ps0;  l1 = l1 * sc1 + ps1;
        m0 = mn0;  m1 = mn1;

        #pragma unroll
        for (int jd = 0; jd < 8; jd++) {
            o[jd][0] *= sc0;  o[jd][1] *= sc0;
            o[jd][2] *= sc1;  o[jd][3] *= sc1;
        }
        __syncwarp();

        #pragma unroll
        for (int ks = 0; ks < 8; ks++) {
            uint32_t ap[4];
            int r0 = w*16 + gr;
            ap[0] = __float_as_uint(QPs[r0    ][8*ks + gc    ]);
            ap[1] = __float_as_uint(QPs[r0 + 8][8*ks + gc    ]);
            ap[2] = __float_as_uint(QPs[r0    ][8*ks + gc + 4]);
            ap[3] = __float_as_uint(QPs[r0 + 8][8*ks + gc + 4]);
            #pragma unroll
            for (int jd = 0; jd < 8; jd++) {
                uint32_t bv[2];
                bv[0] = __float_as_uint(Vs[8*ks + gc    ][jd*8 + gr]);
                bv[1] = __float_as_uint(Vs[8*ks + gc + 4][jd*8 + gr]);
                mma_tf32(o[jd], ap, bv);
            }
        }
        __syncthreads();
    }

    float i0 = 1.0f / l0, i1 = 1.0f / l1;
    #pragma unroll
    for (int jd = 0; jd < 8; jd++) {
        int d = jd*8 + gc*2;
        float* op = ctx + ((size_t)(b * S_ + rowg) * HID_ + h * D_ + d);
        *(float2*)op              = make_float2(o[jd][0] * i0, o[jd][1] * i0);
        *(float2*)(op + 8 * HID_) = make_float2(o[jd][2] * i1, o[jd][3] * i1);
    }
}

// ---------------------------------------------------------------------------
extern "C" void kernel_launch(void* const* d_in, const int* in_sizes, int n_in,
                              void* d_out, int out_size)
{
    const float* hid  = (const float*)d_in[0];
    const float* mask = (const float*)d_in[1];
    const float* Wq   = (const float*)d_in[2];
    const float* bq   = (const float*)d_in[3];
    const float* Wk   = (const float*)d_in[4];
    const float* bk   = (const float*)d_in[5];
    const float* Wv   = (const float*)d_in[6];
    const float* bv   = (const float*)d_in[7];
    float* out = (float*)d_out;

    // 1) Q,K,V projections (3xTF32 MMA, interleaved hi/lo, 128x128 tiles)
    qkv_mma<<<dim3(HID_ / 128, BS_ / 128, 3), 256>>>(hid, Wq, bq, Wk, bk, Wv, bv);

    // 2) qq / kk / vv self-similarity scores
    scores_sim<<<dim3(S_ / 128, S_ / 64, 3 * BH_), 256>>>(mask, out + CTX_ELEMS);

    // 3) fused qk scores + softmax + P@V -> scores(qk) region + ctx
    flash_attn<<<dim3(S_ / 64, BH_), 128>>>(mask, out + CTX_ELEMS, out);
}

// round 6
// speedup vs baseline: 1.3908x; 1.3908x over previous
#include <cuda_runtime.h>
#include <cuda_bf16.h>
#include <math.h>
#include <stdint.h>

#define B_   8
#define S_   512
#define HID_ 768
#define H_   12
#define D_   64
#define BS_  (B_*S_)          // 4096
#define BH_  (B_*H_)          // 96

#define CTX_ELEMS ((size_t)B_*S_*HID_)        // 3,145,728
#define SC_ELEMS  ((size_t)BH_*S_*S_)         // 25,165,824

#define HPAIRS ((size_t)BS_*HID_/2)           // 1,572,864
#define WPAIRS ((size_t)HID_*HID_/2)          //   294,912
#define ROWP   (HID_/2)                       // 384 pairs per row

// Scratch (device globals — no allocation in kernel_launch)
__device__ float g_q[BH_*S_*D_];
__device__ float g_k[BH_*S_*D_];
__device__ float g_v[BH_*S_*D_];
__device__ uint2 g_hidP[HPAIRS];              // (bf16x2 hi, bf16x2 lo) per k-pair
__device__ uint2 g_WP[3][WPAIRS];

__device__ __forceinline__ float to_tf32(float x) {
    float r;
    asm("cvt.rna.tf32.f32 %0, %1;" : "=f"(r) : "f"(x));
    return r;
}

__device__ __forceinline__ void mma_tf32(float* c, const uint32_t* a, const uint32_t* b) {
    asm volatile(
        "mma.sync.aligned.m16n8k8.row.col.f32.tf32.tf32.f32 "
        "{%0,%1,%2,%3}, {%4,%5,%6,%7}, {%8,%9}, {%0,%1,%2,%3};\n"
        : "+f"(c[0]), "+f"(c[1]), "+f"(c[2]), "+f"(c[3])
        : "r"(a[0]), "r"(a[1]), "r"(a[2]), "r"(a[3]), "r"(b[0]), "r"(b[1]));
}

__device__ __forceinline__ void mma_bf16(float* c, const uint32_t* a, const uint32_t* b) {
    asm volatile(
        "mma.sync.aligned.m16n8k16.row.col.f32.bf16.bf16.f32 "
        "{%0,%1,%2,%3}, {%4,%5,%6,%7}, {%8,%9}, {%0,%1,%2,%3};\n"
        : "+f"(c[0]), "+f"(c[1]), "+f"(c[2]), "+f"(c[3])
        : "r"(a[0]), "r"(a[1]), "r"(a[2]), "r"(a[3]), "r"(b[0]), "r"(b[1]));
}

__device__ __forceinline__ uint32_t smem_u32(const void* p) {
    return (uint32_t)__cvta_generic_to_shared(p);
}

__device__ __forceinline__ void cp16(uint32_t dst, const void* src) {
    asm volatile("cp.async.ca.shared.global [%0], [%1], 16;\n" :: "r"(dst), "l"(src));
}

// ---------------------------------------------------------------------------
// Kernel 0: split hid and W into 2-term bf16 (hi, lo) pair format.
// Memory-bound: ~40MB traffic. One pair (2 fp32) per thread.
// ---------------------------------------------------------------------------
__global__ void __launch_bounds__(256)
split_prep(const float* __restrict__ hid, const float* __restrict__ Wq,
           const float* __restrict__ Wk,  const float* __restrict__ Wv)
{
    size_t i = (size_t)blockIdx.x * 256 + threadIdx.x;
    float2 v;
    uint2* dst;
    if (i < HPAIRS) {
        v = ((const float2*)hid)[i];
        dst = &g_hidP[i];
    } else {
        size_t j = i - HPAIRS;
        int w = (int)(j / WPAIRS);
        size_t o = j - (size_t)w * WPAIRS;
        const float* W = (w == 0) ? Wq : ((w == 1) ? Wk : Wv);
        v = ((const float2*)W)[o];
        dst = &g_WP[w][o];
    }
    __nv_bfloat162 h;
    h.x = __float2bfloat16_rn(v.x);     // .x = low half of .b32 = even-k element
    h.y = __float2bfloat16_rn(v.y);
    float r0 = v.x - __bfloat162float(h.x);
    float r1 = v.y - __bfloat162float(h.y);
    __nv_bfloat162 l;
    l.x = __float2bfloat16_rn(r0);
    l.y = __float2bfloat16_rn(r1);
    uint2 o2;
    o2.x = *(uint32_t*)&h;
    o2.y = *(uint32_t*)&l;
    *dst = o2;
}

// ---------------------------------------------------------------------------
// Kernel 1: QKV projection via 2-term bf16 MMA (3x m16n8k16, ~fp32 accuracy).
// Inner loop: pure cp.async + LDS.64 + HMMA — split done in split_prep.
// Block 128(m) x 128(n), BK=32, double-buffered. 8 warps (2m x 4n), warp 64x32.
// Smem row stride 40 words: conflict-free LDS.64 fragment loads.
// grid: (6, 32, 3).
// ---------------------------------------------------------------------------
__global__ void __launch_bounds__(256, 2)
qkv_mma(const float* __restrict__ bq, const float* __restrict__ bk,
        const float* __restrict__ bv)
{
    const int z = blockIdx.z;
    const uint2* Wp   = g_WP[z];
    const float* bias = (z == 0) ? bq : ((z == 1) ? bk : bv);
    float* out        = (z == 0) ? g_q : ((z == 1) ? g_k : g_v);

    const int m0 = blockIdx.y * 128;
    const int n0 = blockIdx.x * 128;

    // [buf][row][word]: word = 2*pair + (0:hi,1:lo); 16 pairs (k32) + 8 pad
    __shared__ __align__(16) uint32_t As[2][128][40];
    __shared__ __align__(16) uint32_t Bs[2][128][40];

    const int tid  = threadIdx.x;
    const int lane = tid & 31;
    const int wid  = tid >> 5;
    const int gr   = lane >> 2;
    const int gc   = lane & 3;
    const int wm   = (wid & 1) * 64;
    const int wn   = (wid >> 1) * 32;

    float c[4][4][4];
    #pragma unroll
    for (int im = 0; im < 4; im++)
        #pragma unroll
        for (int jn = 0; jn < 4; jn++)
            #pragma unroll
            for (int r = 0; r < 4; r++) c[im][jn][r] = 0.0f;

    // stage = k32 = 16 pairs = 128B/row = 8 x 16B chunks; 1024 chunks per matrix
    #define LOAD_STAGE(buf, kp0)                                                 \
    {                                                                            \
        _Pragma("unroll")                                                        \
        for (int r = 0; r < 4; r++) {                                            \
            int cc = tid + 256 * r; int row = cc >> 3; int sub = cc & 7;         \
            cp16(smem_u32(&As[buf][row][sub * 4]),                               \
                 g_hidP + (size_t)(m0 + row) * ROWP + (kp0) + sub * 2);          \
        }                                                                        \
        _Pragma("unroll")                                                        \
        for (int r = 0; r < 4; r++) {                                            \
            int cc = tid + 256 * r; int row = cc >> 3; int sub = cc & 7;         \
            cp16(smem_u32(&Bs[buf][row][sub * 4]),                               \
                 Wp + (size_t)(n0 + row) * ROWP + (kp0) + sub * 2);              \
        }                                                                        \
        asm volatile("cp.async.commit_group;\n");                                \
    }

    LOAD_STAGE(0, 0)

    const int NIT = HID_ / 32;   // 24 stages of k32
    for (int it = 0; it < NIT; it++) {
        asm volatile("cp.async.wait_group 0;\n");
        __syncthreads();                       // stage `it` visible; prev compute done
        if (it + 1 < NIT) { LOAD_STAGE((it + 1) & 1, (it + 1) * 16) }

        const int buf = it & 1;
        #pragma unroll
        for (int ks = 0; ks < 2; ks++) {       // two k16 steps per stage
            const int c0 = 2 * gc + 16 * ks;   // word offset of pair gc
            uint32_t ahi[4][4], alo[4][4];
            #pragma unroll
            for (int im = 0; im < 4; im++) {
                int r = wm + im * 16 + gr;
                uint2 t;
                t = *(const uint2*)&As[buf][r    ][c0    ]; ahi[im][0] = t.x; alo[im][0] = t.y;
                t = *(const uint2*)&As[buf][r + 8][c0    ]; ahi[im][1] = t.x; alo[im][1] = t.y;
                t = *(const uint2*)&As[buf][r    ][c0 + 8]; ahi[im][2] = t.x; alo[im][2] = t.y;
                t = *(const uint2*)&As[buf][r + 8][c0 + 8]; ahi[im][3] = t.x; alo[im][3] = t.y;
            }
            #pragma unroll
            for (int jn = 0; jn < 4; jn++) {
                int n = wn + jn * 8 + gr;
                uint2 t0 = *(const uint2*)&Bs[buf][n][c0    ];
                uint2 t1 = *(const uint2*)&Bs[buf][n][c0 + 8];
                uint32_t bhi[2] = {t0.x, t1.x};
                uint32_t blo[2] = {t0.y, t1.y};
                #pragma unroll
                for (int im = 0; im < 4; im++) {
                    mma_bf16(c[im][jn], ahi[im], bhi);
                    mma_bf16(c[im][jn], ahi[im], blo);
                    mma_bf16(c[im][jn], alo[im], bhi);
                }
            }
        }
        __syncthreads();
    }
    #undef LOAD_STAGE

    // Epilogue: + bias, scatter to [B,H,S,D]. Warp n-span (32) never crosses a head.
    const int h      = (n0 + wn) >> 6;
    const int d_base = (n0 + wn) & 63;
    #pragma unroll
    for (int jn = 0; jn < 4; jn++) {
        int d = d_base + jn * 8 + gc * 2;
        float b0 = bias[n0 + wn + jn * 8 + gc * 2];
        float b1 = bias[n0 + wn + jn * 8 + gc * 2 + 1];
        #pragma unroll
        for (int im = 0; im < 4; im++) {
            int m = m0 + wm + im * 16 + gr;
            int b = m >> 9;
            int s = m & 511;
            float* o = out + (((size_t)(b * H_ + h) * S_ + s) * D_ + d);
            *(float2*)o            = make_float2(c[im][jn][0] + b0, c[im][jn][1] + b1);
            *(float2*)(o + 8 * D_) = make_float2(c[im][jn][2] + b0, c[im][jn][3] + b1);
        }
    }
}

// ---------------------------------------------------------------------------
// Kernel 2: self-similarity scores (qq, kk, vv) via tf32 mma.
// C = 0.125*X@X^T + mask. Block: 64(q) x 128(k), 256 threads (8 warps 2x4).
// grid: (4, 8, 3*96).   [unchanged from R4 — validated]
// ---------------------------------------------------------------------------
__global__ void __launch_bounds__(256)
scores_sim(const float* __restrict__ mask, float* __restrict__ out_base)
{
    const int z    = blockIdx.z;
    const int type = 1 + z / BH_;       // 1:qq 2:kk 3:vv
    const int bh   = z % BH_;

    const float* X = (type == 1) ? g_q : ((type == 2) ? g_k : g_v);
    X += (size_t)bh * S_ * D_;

    float* out = out_base + (size_t)type * SC_ELEMS + (size_t)bh * S_ * S_;
    const float* mrow = mask + (size_t)(bh / H_) * S_;

    const int m0 = blockIdx.y * 64;
    const int n0 = blockIdx.x * 128;

    __shared__ float Xs[64][68];
    __shared__ float Ys[128][68];

    const int tid = threadIdx.x;

    #pragma unroll
    for (int r = 0; r < 4; r++) {
        int idx = tid + 256 * r;
        int row = idx >> 4;
        int q   = idx & 15;
        float4 a = *(const float4*)(X + (size_t)(m0 + row) * D_ + q * 4);
        Xs[row][q*4+0] = to_tf32(a.x); Xs[row][q*4+1] = to_tf32(a.y);
        Xs[row][q*4+2] = to_tf32(a.z); Xs[row][q*4+3] = to_tf32(a.w);
    }
    #pragma unroll
    for (int r = 0; r < 8; r++) {
        int idx = tid + 256 * r;
        int row = idx >> 4;
        int q   = idx & 15;
        float4 b = *(const float4*)(X + (size_t)(n0 + row) * D_ + q * 4);
        Ys[row][q*4+0] = to_tf32(b.x); Ys[row][q*4+1] = to_tf32(b.y);
        Ys[row][q*4+2] = to_tf32(b.z); Ys[row][q*4+3] = to_tf32(b.w);
    }
    __syncthreads();

    const int lane = tid & 31;
    const int wid  = tid >> 5;
    const int wm   = (wid & 1) * 32;
    const int wn   = (wid >> 1) * 32;
    const int gr   = lane >> 2;
    const int gc   = lane & 3;

    float c[2][4][4];
    #pragma unroll
    for (int im = 0; im < 2; im++)
        #pragma unroll
        for (int jn = 0; jn < 4; jn++)
            #pragma unroll
            for (int r = 0; r < 4; r++) c[im][jn][r] = 0.0f;

    #pragma unroll
    for (int k0 = 0; k0 < 64; k0 += 8) {
        uint32_t a[2][4], b[4][2];
        #pragma unroll
        for (int im = 0; im < 2; im++) {
            int r0 = wm + im * 16 + gr;
            a[im][0] = __float_as_uint(Xs[r0    ][k0 + gc    ]);
            a[im][1] = __float_as_uint(Xs[r0 + 8][k0 + gc    ]);
            a[im][2] = __float_as_uint(Xs[r0    ][k0 + gc + 4]);
            a[im][3] = __float_as_uint(Xs[r0 + 8][k0 + gc + 4]);
        }
        #pragma unroll
        for (int jn = 0; jn < 4; jn++) {
            int n = wn + jn * 8 + gr;
            b[jn][0] = __float_as_uint(Ys[n][k0 + gc    ]);
            b[jn][1] = __float_as_uint(Ys[n][k0 + gc + 4]);
        }
        #pragma unroll
        for (int im = 0; im < 2; im++)
            #pragma unroll
            for (int jn = 0; jn < 4; jn++)
                mma_tf32(c[im][jn], a[im], b[jn]);
    }

    #pragma unroll
    for (int im = 0; im < 2; im++) {
        #pragma unroll
        for (int jn = 0; jn < 4; jn++) {
            int row = m0 + wm + im * 16 + gr;
            int col = n0 + wn + jn * 8 + gc * 2;
            float mv0 = mrow[col], mv1 = mrow[col + 1];
            float2 o0 = make_float2(c[im][jn][0] * 0.125f + mv0,
                                    c[im][jn][1] * 0.125f + mv1);
            float2 o1 = make_float2(c[im][jn][2] * 0.125f + mv0,
                                    c[im][jn][3] * 0.125f + mv1);
            *(float2*)(out + (size_t)row * S_ + col)       = o0;
            *(float2*)(out + (size_t)(row + 8) * S_ + col) = o1;
        }
    }
}

// ---------------------------------------------------------------------------
// Kernel 3: fused qk-scores + softmax + P@V, all-MMA (tf32).
// grid: (8, 96).   [unchanged from R4 — validated]
// ---------------------------------------------------------------------------
__global__ void __launch_bounds__(128)
flash_attn(const float* __restrict__ mask, float* __restrict__ sout_base,
           float* __restrict__ ctx)
{
    const int bh = blockIdx.y;
    const int q0 = blockIdx.x * 64;
    const int b  = bh / H_;
    const int h  = bh - b * H_;
    const float* Qp = g_q + (size_t)bh * S_ * D_;
    const float* Kp = g_k + (size_t)bh * S_ * D_;
    const float* Vp = g_v + (size_t)bh * S_ * D_;
    float* sout = sout_base + (size_t)bh * S_ * S_;
    const float* mrow = mask + (size_t)b * S_;

    __shared__ float QPs[64][68];
    __shared__ float Ks[64][68];
    __shared__ float Vs[64][72];

    const int tid  = threadIdx.x;
    const int lane = tid & 31;
    const int w    = tid >> 5;
    const int gr   = lane >> 2;
    const int gc   = lane & 3;

    #pragma unroll
    for (int r = 0; r < 8; r++) {
        int idx = tid + 128 * r;
        int row = idx >> 4;
        int q   = idx & 15;
        float4 a = *(const float4*)(Qp + (size_t)(q0 + row) * D_ + q * 4);
        QPs[row][q*4+0] = to_tf32(a.x); QPs[row][q*4+1] = to_tf32(a.y);
        QPs[row][q*4+2] = to_tf32(a.z); QPs[row][q*4+3] = to_tf32(a.w);
    }
    __syncthreads();

    uint32_t aq[8][4];
    #pragma unroll
    for (int ks = 0; ks < 8; ks++) {
        int r0 = w * 16 + gr;
        aq[ks][0] = __float_as_uint(QPs[r0    ][8*ks + gc    ]);
        aq[ks][1] = __float_as_uint(QPs[r0 + 8][8*ks + gc    ]);
        aq[ks][2] = __float_as_uint(QPs[r0    ][8*ks + gc + 4]);
        aq[ks][3] = __float_as_uint(QPs[r0 + 8][8*ks + gc + 4]);
    }

    float o[8][4];
    #pragma unroll
    for (int jd = 0; jd < 8; jd++)
        #pragma unroll
        for (int r = 0; r < 4; r++) o[jd][r] = 0.0f;

    float m0 = -1e30f, m1 = -1e30f, l0 = 0.0f, l1 = 0.0f;
    const int rowg = q0 + w * 16 + gr;

    for (int kt = 0; kt < 8; kt++) {
        #pragma unroll
        for (int r = 0; r < 8; r++) {
            int idx = tid + 128 * r;
            int row = idx >> 4;
            int q   = idx & 15;
            float4 kv = *(const float4*)(Kp + (size_t)(kt*64 + row) * D_ + q * 4);
            Ks[row][q*4+0] = to_tf32(kv.x); Ks[row][q*4+1] = to_tf32(kv.y);
            Ks[row][q*4+2] = to_tf32(kv.z); Ks[row][q*4+3] = to_tf32(kv.w);
            float4 vv = *(const float4*)(Vp + (size_t)(kt*64 + row) * D_ + q * 4);
            Vs[row][q*4+0] = to_tf32(vv.x); Vs[row][q*4+1] = to_tf32(vv.y);
            Vs[row][q*4+2] = to_tf32(vv.z); Vs[row][q*4+3] = to_tf32(vv.w);
        }
        __syncthreads();

        float s[8][4];
        #pragma unroll
        for (int jn = 0; jn < 8; jn++) {
            #pragma unroll
            for (int r = 0; r < 4; r++) s[jn][r] = 0.0f;
            #pragma unroll
            for (int ks = 0; ks < 8; ks++) {
                uint32_t bv[2];
                bv[0] = __float_as_uint(Ks[jn*8 + gr][8*ks + gc    ]);
                bv[1] = __float_as_uint(Ks[jn*8 + gr][8*ks + gc + 4]);
                mma_tf32(s[jn], aq[ks], bv);
            }
        }

        float mx0 = -1e30f, mx1 = -1e30f;
        #pragma unroll
        for (int jn = 0; jn < 8; jn++) {
            int col = kt*64 + jn*8 + gc*2;
            float mv0 = mrow[col], mv1 = mrow[col + 1];
            s[jn][0] = s[jn][0]*0.125f + mv0;  s[jn][1] = s[jn][1]*0.125f + mv1;
            s[jn][2] = s[jn][2]*0.125f + mv0;  s[jn][3] = s[jn][3]*0.125f + mv1;
            *(float2*)(sout + (size_t)rowg       * S_ + col) = make_float2(s[jn][0], s[jn][1]);
            *(float2*)(sout + (size_t)(rowg + 8) * S_ + col) = make_float2(s[jn][2], s[jn][3]);
            mx0 = fmaxf(mx0, fmaxf(s[jn][0], s[jn][1]));
            mx1 = fmaxf(mx1, fmaxf(s[jn][2], s[jn][3]));
        }
        mx0 = fmaxf(mx0, __shfl_xor_sync(0xffffffffu, mx0, 1));
        mx0 = fmaxf(mx0, __shfl_xor_sync(0xffffffffu, mx0, 2));
        mx1 = fmaxf(mx1, __shfl_xor_sync(0xffffffffu, mx1, 1));
        mx1 = fmaxf(mx1, __shfl_xor_sync(0xffffffffu, mx1, 2));

        float mn0 = fmaxf(m0, mx0), mn1 = fmaxf(m1, mx1);
        float sc0 = __expf(m0 - mn0), sc1 = __expf(m1 - mn1);

        float ps0 = 0.0f, ps1 = 0.0f;
        #pragma unroll
        for (int jn = 0; jn < 8; jn++) {
            float p0 = __expf(s[jn][0] - mn0), p1 = __expf(s[jn][1] - mn0);
            float p2 = __expf(s[jn][2] - mn1), p3 = __expf(s[jn][3] - mn1);
            ps0 += p0 + p1;  ps1 += p2 + p3;
            int col = jn*8 + gc*2;
            int r0  = w*16 + gr;
            *(float2*)&QPs[r0    ][col] = make_float2(to_tf32(p0), to_tf32(p1));
            *(float2*)&QPs[r0 + 8][col] = make_float2(to_tf32(p2), to_tf32(p3));
        }
        ps0 += __shfl_xor_sync(0xffffffffu, ps0, 1);
        ps0 += __shfl_xor_sync(0xffffffffu, ps0, 2);
        ps1 += __shfl_xor_sync(0xffffffffu, ps1, 1);
        ps1 += __shfl_xor_sync(0xffffffffu, ps1, 2);
        l0 = l0 * sc0 + ps0;  l1 = l1 * sc1 + ps1;
        m0 = mn0;  m1 = mn1;

        #pragma unroll
        for (int jd = 0; jd < 8; jd++) {
            o[jd][0] *= sc0;  o[jd][1] *= sc0;
            o[jd][2] *= sc1;  o[jd][3] *= sc1;
        }
        __syncwarp();

        #pragma unroll
        for (int ks = 0; ks < 8; ks++) {
            uint32_t ap[4];
            int r0 = w*16 + gr;
            ap[0] = __float_as_uint(QPs[r0    ][8*ks + gc    ]);
            ap[1] = __float_as_uint(QPs[r0 + 8][8*ks + gc    ]);
            ap[2] = __float_as_uint(QPs[r0    ][8*ks + gc + 4]);
            ap[3] = __float_as_uint(QPs[r0 + 8][8*ks + gc + 4]);
            #pragma unroll
            for (int jd = 0; jd < 8; jd++) {
                uint32_t bv[2];
                bv[0] = __float_as_uint(Vs[8*ks + gc    ][jd*8 + gr]);
                bv[1] = __float_as_uint(Vs[8*ks + gc + 4][jd*8 + gr]);
                mma_tf32(o[jd], ap, bv);
            }
        }
        __syncthreads();
    }

    float i0 = 1.0f / l0, i1 = 1.0f / l1;
    #pragma unroll
    for (int jd = 0; jd < 8; jd++) {
        int d = jd*8 + gc*2;
        float* op = ctx + ((size_t)(b * S_ + rowg) * HID_ + h * D_ + d);
        *(float2*)op              = make_float2(o[jd][0] * i0, o[jd][1] * i0);
        *(float2*)(op + 8 * HID_) = make_float2(o[jd][2] * i1, o[jd][3] * i1);
    }
}

// ---------------------------------------------------------------------------
extern "C" void kernel_launch(void* const* d_in, const int* in_sizes, int n_in,
                              void* d_out, int out_size)
{
    const float* hid  = (const float*)d_in[0];
    const float* mask = (const float*)d_in[1];
    const float* Wq   = (const float*)d_in[2];
    const float* bq   = (const float*)d_in[3];
    const float* Wk   = (const float*)d_in[4];
    const float* bk   = (const float*)d_in[5];
    const float* Wv   = (const float*)d_in[6];
    const float* bv   = (const float*)d_in[7];
    float* out = (float*)d_out;

    // 0) split hid/W into bf16 (hi,lo) pair format
    const int nprep = (int)((HPAIRS + 3 * WPAIRS) / 256);   // 9600
    split_prep<<<nprep, 256>>>(hid, Wq, Wk, Wv);

    // 1) Q,K,V projections (2-term bf16, 3x m16n8k16 MMA)
    qkv_mma<<<dim3(HID_ / 128, BS_ / 128, 3), 256>>>(bq, bk, bv);

    // 2) qq / kk / vv self-similarity scores
    scores_sim<<<dim3(S_ / 128, S_ / 64, 3 * BH_), 256>>>(mask, out + CTX_ELEMS);

    // 3) fused qk scores + softmax + P@V -> scores(qk) region + ctx
    flash_attn<<<dim3(S_ / 64, BH_), 128>>>(mask, out + CTX_ELEMS, out);
}